// round 3
// baseline (speedup 1.0000x reference)
#include <cuda_runtime.h>
#include <math.h>

#define F_IN  1433
#define F_HID 16
#define NMAX  100000
#define EMAX  3200000
#define SROW  18   // padded smem row (floats): 8B-aligned

// Scratch (device globals; allocation is forbidden)
__device__ __align__(16) float g_dis [NMAX];
__device__ int   g_is64;
__device__ int   g_cnt[NMAX];
__device__ int   g_off[NMAX + 1];
__device__ int   g_cur[NMAX];
__device__ int   g_src[EMAX];
__device__ __align__(16) float g_h1  [NMAX * 16];
__device__ __align__(16) float g_agg1[NMAX * 16];
__device__ __align__(16) float g_h2  [NMAX * 8];
__device__ __align__(16) float g_agg2[NMAX * 8];

typedef unsigned long long u64;
__device__ __forceinline__ u64 pack2(float lo, float hi) {
    u64 r; asm("mov.b64 %0, {%1,%2};" : "=l"(r) : "f"(lo), "f"(hi)); return r;
}
__device__ __forceinline__ void unpack2(u64 v, float& lo, float& hi) {
    asm("mov.b64 {%0,%1}, %2;" : "=f"(lo), "=f"(hi) : "l"(v));
}
__device__ __forceinline__ void fma2(u64& d, u64 a, u64 b) {
    asm("fma.rn.f32x2 %0, %1, %2, %0;" : "+l"(d) : "l"(a), "l"(b));
}
__device__ __forceinline__ void add2(u64& d, u64 a) {
    asm("add.rn.f32x2 %0, %0, %1;" : "+l"(d) : "l"(a));
}

// ---------------------------------------------------------------------------
// Dtype probe: int64 edge_index has zero high words (values < 2^31)
// ---------------------------------------------------------------------------
__global__ void k_probe(const int* __restrict__ ei32, int nwords) {
    if (threadIdx.x != 0 || blockIdx.x != 0) return;
    int is64 = 1;
    int lim = nwords < 256 ? nwords : 256;
    for (int i = 1; i < lim; i += 2)
        if (ei32[i] != 0) { is64 = 0; break; }
    g_is64 = is64;
}

__device__ __forceinline__ int edge_at(const int* ei32, int idx, int is64) {
    if (is64) return (int)reinterpret_cast<const long long*>(ei32)[idx];
    return ei32[idx];
}

// ---------------------------------------------------------------------------
// CSR build
// ---------------------------------------------------------------------------
__global__ void k_zero(int n) {
    int i = blockIdx.x * blockDim.x + threadIdx.x;
    if (i < n) g_cnt[i] = 0;
}

__global__ void k_count(const int* __restrict__ ei, int E) {
    int e = blockIdx.x * blockDim.x + threadIdx.x;
    if (e >= E) return;
    int is64 = g_is64;
    int d = edge_at(ei, E + e, is64);
    atomicAdd(&g_cnt[d], 1);
}

__global__ void k_scan(int n) {
    __shared__ int ssum[1024];
    int tid = threadIdx.x;
    int CH = (n + 1023) >> 10;
    int start = tid * CH;
    int end = start + CH; if (end > n) end = n;
    int s = 0;
    for (int i = start; i < end; ++i) s += g_cnt[i];
    ssum[tid] = s;
    __syncthreads();
    for (int off = 1; off < 1024; off <<= 1) {
        int t = (tid >= off) ? ssum[tid - off] : 0;
        __syncthreads();
        ssum[tid] += t;
        __syncthreads();
    }
    int run = ssum[tid] - s;  // exclusive prefix
    for (int i = start; i < end; ++i) {
        g_off[i] = run; g_cur[i] = run; run += g_cnt[i];
    }
    if (tid == 1023) g_off[n] = ssum[1023];
}

__global__ void k_fill(const int* __restrict__ ei, int E) {
    int e = blockIdx.x * blockDim.x + threadIdx.x;
    if (e >= E) return;
    int is64 = g_is64;
    int s = edge_at(ei, e, is64);
    int d = edge_at(ei, E + e, is64);
    int p = atomicAdd(&g_cur[d], 1);
    g_src[p] = s;
}

__global__ void k_dis(int n) {
    int i = blockIdx.x * blockDim.x + threadIdx.x;
    if (i < n) g_dis[i] = rsqrtf((float)g_cnt[i] + 1.0f);  // +1 self-loop
}

// ---------------------------------------------------------------------------
// GEMM1: h1 = x @ W1  via packed f32x2 FMA, W1 staged in smem [k][18]
// warp computes 4 rows; acc[r][p] packs columns (2p, 2p+1)
// ---------------------------------------------------------------------------
__global__ void __launch_bounds__(512, 1) k_gemm1(const float* __restrict__ x,
                                                  const float* __restrict__ W1,
                                                  int n) {
    extern __shared__ float sw[];  // [F_IN][SROW]
    const int tid = threadIdx.x;
    for (int idx = tid; idx < F_IN * F_HID; idx += 512) {
        int k = idx >> 4, j = idx & 15;
        sw[k * SROW + j] = W1[idx];
    }
    __syncthreads();

    const int warp = tid >> 5, lane = tid & 31;
    const int r0 = (blockIdx.x * 16 + warp) * 4;
    if (r0 >= n) return;
    const int r1 = (r0 + 1 < n) ? r0 + 1 : r0;
    const int r2 = (r0 + 2 < n) ? r0 + 2 : r0;
    const int r3 = (r0 + 3 < n) ? r0 + 3 : r0;
    const float* xp0 = x + (size_t)r0 * F_IN;
    const float* xp1 = x + (size_t)r1 * F_IN;
    const float* xp2 = x + (size_t)r2 * F_IN;
    const float* xp3 = x + (size_t)r3 * F_IN;

    u64 acc[4][8];
#pragma unroll
    for (int r = 0; r < 4; ++r)
#pragma unroll
        for (int p = 0; p < 8; ++p) acc[r][p] = 0ull;

#pragma unroll 2
    for (int k = lane; k < F_IN; k += 32) {
        float x0 = xp0[k], x1 = xp1[k], x2 = xp2[k], x3 = xp3[k];
        u64 xx0 = pack2(x0, x0), xx1 = pack2(x1, x1);
        u64 xx2 = pack2(x2, x2), xx3 = pack2(x3, x3);
        const u64* wrow = reinterpret_cast<const u64*>(&sw[k * SROW]);
#pragma unroll
        for (int p = 0; p < 8; ++p) {
            u64 w = wrow[p];
            fma2(acc[0][p], xx0, w);
            fma2(acc[1][p], xx1, w);
            fma2(acc[2][p], xx2, w);
            fma2(acc[3][p], xx3, w);
        }
    }

#pragma unroll
    for (int r = 0; r < 4; ++r) {
#pragma unroll
        for (int p = 0; p < 8; ++p) {
            u64 v = acc[r][p];
#pragma unroll
            for (int off = 16; off > 0; off >>= 1) {
                u64 o = __shfl_xor_sync(0xFFFFFFFFu, v, off);
                add2(v, o);
            }
            if (lane == r * 8 + p && r0 + r < n) {
                float lo, hi; unpack2(v, lo, hi);
                *reinterpret_cast<float2*>(&g_h1[(size_t)(r0 + r) * 16 + 2 * p]) =
                    make_float2(lo, hi);
            }
        }
    }
}

// ---------------------------------------------------------------------------
// Aggregation layer 1 (gather): agg1[i] = dis[i]*sum_{s in N(i)} h1[s]*dis[s]
//                                        + h1[i]*dis[i]^2
// warp per node: 8 edge-slots x 4 quarters
// ---------------------------------------------------------------------------
__global__ void k_agg1(int n) {
    int gw = (blockIdx.x * blockDim.x + threadIdx.x) >> 5;
    if (gw >= n) return;
    int lane = threadIdx.x & 31;
    int slot = lane >> 2, q = lane & 3;
    int beg = g_off[gw], end = g_off[gw + 1];
    float4 acc = make_float4(0.f, 0.f, 0.f, 0.f);
    for (int idx = beg + slot; idx < end; idx += 8) {
        int s = g_src[idx];
        float w = g_dis[s];
        float4 h = reinterpret_cast<const float4*>(g_h1)[s * 4 + q];
        acc.x = fmaf(h.x, w, acc.x);
        acc.y = fmaf(h.y, w, acc.y);
        acc.z = fmaf(h.z, w, acc.z);
        acc.w = fmaf(h.w, w, acc.w);
    }
#pragma unroll
    for (int off = 4; off <= 16; off <<= 1) {
        acc.x += __shfl_xor_sync(0xFFFFFFFFu, acc.x, off);
        acc.y += __shfl_xor_sync(0xFFFFFFFFu, acc.y, off);
        acc.z += __shfl_xor_sync(0xFFFFFFFFu, acc.z, off);
        acc.w += __shfl_xor_sync(0xFFFFFFFFu, acc.w, off);
    }
    if (slot == 0) {
        float dd = g_dis[gw], s2 = dd * dd;
        float4 h = reinterpret_cast<const float4*>(g_h1)[gw * 4 + q];
        float4 o;
        o.x = acc.x * dd + h.x * s2;
        o.y = acc.y * dd + h.y * s2;
        o.z = acc.z * dd + h.z * s2;
        o.w = acc.w * dd + h.w * s2;
        reinterpret_cast<float4*>(g_agg1)[gw * 4 + q] = o;
    }
}

// ---------------------------------------------------------------------------
// Layer 2 linear: h2 = relu(agg1 + b1) @ W2 (padded to 8 floats)
// ---------------------------------------------------------------------------
__global__ void k_layer2(const float* __restrict__ b1,
                         const float* __restrict__ W2, int n) {
    __shared__ float sb1[16];
    __shared__ float sW2[16 * 7];
    if (threadIdx.x < 16) sb1[threadIdx.x] = b1[threadIdx.x];
    if (threadIdx.x < 16 * 7) sW2[threadIdx.x] = W2[threadIdx.x];
    __syncthreads();

    int i = blockIdx.x * blockDim.x + threadIdx.x;
    if (i >= n) return;

    float v[16];
#pragma unroll
    for (int q = 0; q < 4; ++q) {
        float4 a = reinterpret_cast<const float4*>(g_agg1)[i * 4 + q];
        v[q * 4 + 0] = a.x; v[q * 4 + 1] = a.y; v[q * 4 + 2] = a.z; v[q * 4 + 3] = a.w;
    }
#pragma unroll
    for (int j = 0; j < 16; ++j) v[j] = fmaxf(v[j] + sb1[j], 0.0f);

    float o[7];
#pragma unroll
    for (int c = 0; c < 7; ++c) o[c] = 0.0f;
#pragma unroll
    for (int j = 0; j < 16; ++j) {
        float vj = v[j];
#pragma unroll
        for (int c = 0; c < 7; ++c) o[c] = fmaf(vj, sW2[j * 7 + c], o[c]);
    }
    reinterpret_cast<float4*>(g_h2)[i * 2 + 0] = make_float4(o[0], o[1], o[2], o[3]);
    reinterpret_cast<float4*>(g_h2)[i * 2 + 1] = make_float4(o[4], o[5], o[6], 0.0f);
}

// ---------------------------------------------------------------------------
// Aggregation layer 2 (gather): 16 edge-slots x 2 halves per warp
// ---------------------------------------------------------------------------
__global__ void k_agg2(int n) {
    int gw = (blockIdx.x * blockDim.x + threadIdx.x) >> 5;
    if (gw >= n) return;
    int lane = threadIdx.x & 31;
    int slot = lane >> 1, h = lane & 1;
    int beg = g_off[gw], end = g_off[gw + 1];
    float4 acc = make_float4(0.f, 0.f, 0.f, 0.f);
    for (int idx = beg + slot; idx < end; idx += 16) {
        int s = g_src[idx];
        float w = g_dis[s];
        float4 v = reinterpret_cast<const float4*>(g_h2)[s * 2 + h];
        acc.x = fmaf(v.x, w, acc.x);
        acc.y = fmaf(v.y, w, acc.y);
        acc.z = fmaf(v.z, w, acc.z);
        acc.w = fmaf(v.w, w, acc.w);
    }
#pragma unroll
    for (int off = 2; off <= 16; off <<= 1) {
        acc.x += __shfl_xor_sync(0xFFFFFFFFu, acc.x, off);
        acc.y += __shfl_xor_sync(0xFFFFFFFFu, acc.y, off);
        acc.z += __shfl_xor_sync(0xFFFFFFFFu, acc.z, off);
        acc.w += __shfl_xor_sync(0xFFFFFFFFu, acc.w, off);
    }
    if (slot == 0) {
        float dd = g_dis[gw], s2 = dd * dd;
        float4 v = reinterpret_cast<const float4*>(g_h2)[gw * 2 + h];
        float4 o;
        o.x = acc.x * dd + v.x * s2;
        o.y = acc.y * dd + v.y * s2;
        o.z = acc.z * dd + v.z * s2;
        o.w = acc.w * dd + v.w * s2;
        reinterpret_cast<float4*>(g_agg2)[gw * 2 + h] = o;
    }
}

// ---------------------------------------------------------------------------
// Output: log_softmax(agg2 + b2)
// ---------------------------------------------------------------------------
__global__ void k_out(const float* __restrict__ b2, float* __restrict__ out, int n) {
    __shared__ float sb2[7];
    if (threadIdx.x < 7) sb2[threadIdx.x] = b2[threadIdx.x];
    __syncthreads();
    int i = blockIdx.x * blockDim.x + threadIdx.x;
    if (i >= n) return;
    float v[7];
    float4 a0 = reinterpret_cast<const float4*>(g_agg2)[i * 2 + 0];
    float4 a1 = reinterpret_cast<const float4*>(g_agg2)[i * 2 + 1];
    v[0] = a0.x + sb2[0]; v[1] = a0.y + sb2[1]; v[2] = a0.z + sb2[2]; v[3] = a0.w + sb2[3];
    v[4] = a1.x + sb2[4]; v[5] = a1.y + sb2[5]; v[6] = a1.z + sb2[6];
    float m = v[0];
#pragma unroll
    for (int c = 1; c < 7; ++c) m = fmaxf(m, v[c]);
    float sum = 0.0f;
#pragma unroll
    for (int c = 0; c < 7; ++c) sum += expf(v[c] - m);
    float lse = logf(sum);
#pragma unroll
    for (int c = 0; c < 7; ++c) out[(size_t)i * 7 + c] = v[c] - m - lse;
}

// ---------------------------------------------------------------------------
extern "C" void kernel_launch(void* const* d_in, const int* in_sizes, int n_in,
                              void* d_out, int out_size) {
    const float* x  = (const float*)d_in[0];
    const int*   ei = (const int*)d_in[1];     // int32 OR int64 (probed on device)
    const float* W1 = (const float*)d_in[2];
    const float* b1 = (const float*)d_in[3];
    const float* W2 = (const float*)d_in[4];
    const float* b2 = (const float*)d_in[5];
    float* out = (float*)d_out;

    const int E = in_sizes[1] / 2;      // 3,200,000 edges (element count / 2)
    const int n = in_sizes[0] / F_IN;   // 100,000 nodes

    const int smem = F_IN * SROW * (int)sizeof(float);  // 103,176 B
    cudaFuncSetAttribute(k_gemm1, cudaFuncAttributeMaxDynamicSharedMemorySize, smem);

    const int T = 256;
    k_probe <<<1, 32>>>(ei, in_sizes[1]);
    k_zero  <<<(n + T - 1) / T, T>>>(n);
    k_count <<<(E + T - 1) / T, T>>>(ei, E);
    k_scan  <<<1, 1024>>>(n);
    k_fill  <<<(E + T - 1) / T, T>>>(ei, E);
    k_dis   <<<(n + T - 1) / T, T>>>(n);
    k_gemm1 <<<(n + 63) / 64, 512, smem>>>(x, W1, n);
    k_agg1  <<<(n + 7) / 8, 256>>>(n);
    k_layer2<<<(n + T - 1) / T, T>>>(b1, W2, n);
    k_agg2  <<<(n + 7) / 8, 256>>>(n);
    k_out   <<<(n + T - 1) / T, T>>>(b2, out, n);
}

// round 4
// speedup vs baseline: 1.3929x; 1.3929x over previous
#include <cuda_runtime.h>
#include <math.h>

#define F_IN  1433
#define F_HID 16
#define NMAX  100000
#define EMAX  3200000
#define SROW  18      // padded smem row (floats): 8B-aligned
#define SCAN_BLK 1024 // elements per scan block
#define NB_MAX   128  // >= ceil(NMAX/SCAN_BLK)

// Scratch (device globals; allocation is forbidden)
__device__ __align__(16) float g_dis [NMAX];
__device__ int   g_is64;
__device__ __align__(16) int g_cnt[NMAX];
__device__ int   g_off[NMAX + 1];
__device__ int   g_cur[NMAX];
__device__ int   g_bsum[NB_MAX];
__device__ int   g_bbase[NB_MAX];
__device__ int   g_src[EMAX];
__device__ __align__(16) float g_h1  [NMAX * 16];
__device__ __align__(16) float g_agg1[NMAX * 16];
__device__ __align__(16) float g_h2  [NMAX * 8];
__device__ __align__(16) float g_agg2[NMAX * 8];

typedef unsigned long long u64;
__device__ __forceinline__ u64 pack2(float lo, float hi) {
    u64 r; asm("mov.b64 %0, {%1,%2};" : "=l"(r) : "f"(lo), "f"(hi)); return r;
}
__device__ __forceinline__ void unpack2(u64 v, float& lo, float& hi) {
    asm("mov.b64 {%0,%1}, %2;" : "=f"(lo), "=f"(hi) : "l"(v));
}
__device__ __forceinline__ void fma2(u64& d, u64 a, u64 b) {
    asm("fma.rn.f32x2 %0, %1, %2, %0;" : "+l"(d) : "l"(a), "l"(b));
}
__device__ __forceinline__ void add2(u64& d, u64 a) {
    asm("add.rn.f32x2 %0, %0, %1;" : "+l"(d) : "l"(a));
}

// ---------------------------------------------------------------------------
// Dtype probe: int64 edge_index has zero high words (values < 2^31)
// ---------------------------------------------------------------------------
__global__ void k_probe(const int* __restrict__ ei32, int nwords) {
    if (threadIdx.x != 0 || blockIdx.x != 0) return;
    int is64 = 1;
    int lim = nwords < 256 ? nwords : 256;
    for (int i = 1; i < lim; i += 2)
        if (ei32[i] != 0) { is64 = 0; break; }
    g_is64 = is64;
}

__device__ __forceinline__ int edge_at(const int* ei32, int idx, int is64) {
    if (is64) return (int)reinterpret_cast<const long long*>(ei32)[idx];
    return ei32[idx];
}

// ---------------------------------------------------------------------------
// CSR build
// ---------------------------------------------------------------------------
__global__ void k_zero(int n) {
    int i = blockIdx.x * blockDim.x + threadIdx.x;
    if (i < n) g_cnt[i] = 0;
}

__global__ void k_count(const int* __restrict__ ei, int E) {
    int e = blockIdx.x * blockDim.x + threadIdx.x;
    if (e >= E) return;
    int is64 = g_is64;
    int d = edge_at(ei, E + e, is64);
    atomicAdd(&g_cnt[d], 1);
}

// --- grid-wide exclusive scan of g_cnt -> g_off/g_cur, 3 phases ------------
__global__ void k_blocksum(int n) {  // 256 threads, SCAN_BLK elems per block
    __shared__ int swarp[8];
    int t = threadIdx.x;
    int base = blockIdx.x * SCAN_BLK + t * 4;
    int s = 0;
    if (base + 3 < n) {
        int4 c = *reinterpret_cast<const int4*>(&g_cnt[base]);
        s = c.x + c.y + c.z + c.w;
    } else {
#pragma unroll
        for (int j = 0; j < 4; ++j) if (base + j < n) s += g_cnt[base + j];
    }
#pragma unroll
    for (int off = 16; off > 0; off >>= 1) s += __shfl_xor_sync(~0u, s, off);
    if ((t & 31) == 0) swarp[t >> 5] = s;
    __syncthreads();
    if (t < 8) {
        int v = swarp[t];
#pragma unroll
        for (int off = 4; off > 0; off >>= 1) v += __shfl_xor_sync(0xFFu, v, off);
        if (t == 0) g_bsum[blockIdx.x] = v;
    }
}

__global__ void k_scanbsum(int nb, int n) {  // single block, 128 threads
    __shared__ int swarp[4];
    int t = threadIdx.x;
    int v = (t < nb) ? g_bsum[t] : 0;
    int lane = t & 31, w = t >> 5;
    int incl = v;
#pragma unroll
    for (int off = 1; off < 32; off <<= 1) {
        int o = __shfl_up_sync(~0u, incl, off);
        if (lane >= off) incl += o;
    }
    if (lane == 31) swarp[w] = incl;
    __syncthreads();
    int wbase = 0;
#pragma unroll
    for (int j = 0; j < 4; ++j) wbase += (j < w) ? swarp[j] : 0;
    incl += wbase;
    if (t < nb) g_bbase[t] = incl - v;  // exclusive base per block
    if (t == nb - 1) g_off[n] = incl;   // total edges
}

__global__ void k_offsets(int n) {  // 256 threads, SCAN_BLK elems per block
    __shared__ int swarp[8];
    int t = threadIdx.x;
    int base = blockIdx.x * SCAN_BLK + t * 4;
    int c0 = 0, c1 = 0, c2 = 0, c3 = 0;
    if (base + 3 < n) {
        int4 c = *reinterpret_cast<const int4*>(&g_cnt[base]);
        c0 = c.x; c1 = c.y; c2 = c.z; c3 = c.w;
    } else {
        if (base + 0 < n) c0 = g_cnt[base + 0];
        if (base + 1 < n) c1 = g_cnt[base + 1];
        if (base + 2 < n) c2 = g_cnt[base + 2];
        if (base + 3 < n) c3 = g_cnt[base + 3];
    }
    int tsum = c0 + c1 + c2 + c3;
    int lane = t & 31, w = t >> 5;
    int incl = tsum;
#pragma unroll
    for (int off = 1; off < 32; off <<= 1) {
        int o = __shfl_up_sync(~0u, incl, off);
        if (lane >= off) incl += o;
    }
    if (lane == 31) swarp[w] = incl;
    __syncthreads();
    int wbase = 0;
#pragma unroll
    for (int j = 0; j < 8; ++j) wbase += (j < w) ? swarp[j] : 0;
    int ex = g_bbase[blockIdx.x] + wbase + incl - tsum;  // exclusive prefix at base
    int o0 = ex, o1 = ex + c0, o2 = o1 + c1, o3 = o2 + c2;
    if (base + 3 < n) {
        *reinterpret_cast<int4*>(&g_off[base]) = make_int4(o0, o1, o2, o3);
        *reinterpret_cast<int4*>(&g_cur[base]) = make_int4(o0, o1, o2, o3);
    } else {
        if (base + 0 < n) { g_off[base + 0] = o0; g_cur[base + 0] = o0; }
        if (base + 1 < n) { g_off[base + 1] = o1; g_cur[base + 1] = o1; }
        if (base + 2 < n) { g_off[base + 2] = o2; g_cur[base + 2] = o2; }
        if (base + 3 < n) { g_off[base + 3] = o3; g_cur[base + 3] = o3; }
    }
}

__global__ void k_fill(const int* __restrict__ ei, int E) {
    int e = blockIdx.x * blockDim.x + threadIdx.x;
    if (e >= E) return;
    int is64 = g_is64;
    int s = edge_at(ei, e, is64);
    int d = edge_at(ei, E + e, is64);
    int p = atomicAdd(&g_cur[d], 1);
    g_src[p] = s;
}

__global__ void k_dis(int n) {
    int i = blockIdx.x * blockDim.x + threadIdx.x;
    if (i < n) g_dis[i] = rsqrtf((float)g_cnt[i] + 1.0f);  // +1 self-loop
}

// ---------------------------------------------------------------------------
// GEMM1: h1 = x @ W1  via packed f32x2 FMA, W1 staged in smem [k][18]
// ---------------------------------------------------------------------------
__global__ void __launch_bounds__(512, 1) k_gemm1(const float* __restrict__ x,
                                                  const float* __restrict__ W1,
                                                  int n) {
    extern __shared__ float sw[];  // [F_IN][SROW]
    const int tid = threadIdx.x;
    for (int idx = tid; idx < F_IN * F_HID; idx += 512) {
        int k = idx >> 4, j = idx & 15;
        sw[k * SROW + j] = W1[idx];
    }
    __syncthreads();

    const int warp = tid >> 5, lane = tid & 31;
    const int r0 = (blockIdx.x * 16 + warp) * 4;
    if (r0 >= n) return;
    const int r1 = (r0 + 1 < n) ? r0 + 1 : r0;
    const int r2 = (r0 + 2 < n) ? r0 + 2 : r0;
    const int r3 = (r0 + 3 < n) ? r0 + 3 : r0;
    const float* xp0 = x + (size_t)r0 * F_IN;
    const float* xp1 = x + (size_t)r1 * F_IN;
    const float* xp2 = x + (size_t)r2 * F_IN;
    const float* xp3 = x + (size_t)r3 * F_IN;

    u64 acc[4][8];
#pragma unroll
    for (int r = 0; r < 4; ++r)
#pragma unroll
        for (int p = 0; p < 8; ++p) acc[r][p] = 0ull;

#pragma unroll 2
    for (int k = lane; k < F_IN; k += 32) {
        float x0 = xp0[k], x1 = xp1[k], x2 = xp2[k], x3 = xp3[k];
        u64 xx0 = pack2(x0, x0), xx1 = pack2(x1, x1);
        u64 xx2 = pack2(x2, x2), xx3 = pack2(x3, x3);
        const u64* wrow = reinterpret_cast<const u64*>(&sw[k * SROW]);
#pragma unroll
        for (int p = 0; p < 8; ++p) {
            u64 w = wrow[p];
            fma2(acc[0][p], xx0, w);
            fma2(acc[1][p], xx1, w);
            fma2(acc[2][p], xx2, w);
            fma2(acc[3][p], xx3, w);
        }
    }

#pragma unroll
    for (int r = 0; r < 4; ++r) {
#pragma unroll
        for (int p = 0; p < 8; ++p) {
            u64 v = acc[r][p];
#pragma unroll
            for (int off = 16; off > 0; off >>= 1) {
                u64 o = __shfl_xor_sync(0xFFFFFFFFu, v, off);
                add2(v, o);
            }
            if (lane == r * 8 + p && r0 + r < n) {
                float lo, hi; unpack2(v, lo, hi);
                *reinterpret_cast<float2*>(&g_h1[(size_t)(r0 + r) * 16 + 2 * p]) =
                    make_float2(lo, hi);
            }
        }
    }
}

// ---------------------------------------------------------------------------
// Aggregation layer 1 (gather): warp per node, 8 edge-slots x 4 quarters
// ---------------------------------------------------------------------------
__global__ void k_agg1(int n) {
    int gw = (blockIdx.x * blockDim.x + threadIdx.x) >> 5;
    if (gw >= n) return;
    int lane = threadIdx.x & 31;
    int slot = lane >> 2, q = lane & 3;
    int beg = g_off[gw], end = g_off[gw + 1];
    float4 acc = make_float4(0.f, 0.f, 0.f, 0.f);
    for (int idx = beg + slot; idx < end; idx += 8) {
        int s = g_src[idx];
        float w = g_dis[s];
        float4 h = reinterpret_cast<const float4*>(g_h1)[s * 4 + q];
        acc.x = fmaf(h.x, w, acc.x);
        acc.y = fmaf(h.y, w, acc.y);
        acc.z = fmaf(h.z, w, acc.z);
        acc.w = fmaf(h.w, w, acc.w);
    }
#pragma unroll
    for (int off = 4; off <= 16; off <<= 1) {
        acc.x += __shfl_xor_sync(0xFFFFFFFFu, acc.x, off);
        acc.y += __shfl_xor_sync(0xFFFFFFFFu, acc.y, off);
        acc.z += __shfl_xor_sync(0xFFFFFFFFu, acc.z, off);
        acc.w += __shfl_xor_sync(0xFFFFFFFFu, acc.w, off);
    }
    if (slot == 0) {
        float dd = g_dis[gw], s2 = dd * dd;
        float4 h = reinterpret_cast<const float4*>(g_h1)[gw * 4 + q];
        float4 o;
        o.x = acc.x * dd + h.x * s2;
        o.y = acc.y * dd + h.y * s2;
        o.z = acc.z * dd + h.z * s2;
        o.w = acc.w * dd + h.w * s2;
        reinterpret_cast<float4*>(g_agg1)[gw * 4 + q] = o;
    }
}

// ---------------------------------------------------------------------------
// Layer 2 linear: h2 = relu(agg1 + b1) @ W2 (padded to 8 floats)
// ---------------------------------------------------------------------------
__global__ void k_layer2(const float* __restrict__ b1,
                         const float* __restrict__ W2, int n) {
    __shared__ float sb1[16];
    __shared__ float sW2[16 * 7];
    if (threadIdx.x < 16) sb1[threadIdx.x] = b1[threadIdx.x];
    if (threadIdx.x < 16 * 7) sW2[threadIdx.x] = W2[threadIdx.x];
    __syncthreads();

    int i = blockIdx.x * blockDim.x + threadIdx.x;
    if (i >= n) return;

    float v[16];
#pragma unroll
    for (int q = 0; q < 4; ++q) {
        float4 a = reinterpret_cast<const float4*>(g_agg1)[i * 4 + q];
        v[q * 4 + 0] = a.x; v[q * 4 + 1] = a.y; v[q * 4 + 2] = a.z; v[q * 4 + 3] = a.w;
    }
#pragma unroll
    for (int j = 0; j < 16; ++j) v[j] = fmaxf(v[j] + sb1[j], 0.0f);

    float o[7];
#pragma unroll
    for (int c = 0; c < 7; ++c) o[c] = 0.0f;
#pragma unroll
    for (int j = 0; j < 16; ++j) {
        float vj = v[j];
#pragma unroll
        for (int c = 0; c < 7; ++c) o[c] = fmaf(vj, sW2[j * 7 + c], o[c]);
    }
    reinterpret_cast<float4*>(g_h2)[i * 2 + 0] = make_float4(o[0], o[1], o[2], o[3]);
    reinterpret_cast<float4*>(g_h2)[i * 2 + 1] = make_float4(o[4], o[5], o[6], 0.0f);
}

// ---------------------------------------------------------------------------
// Aggregation layer 2 (gather): 16 edge-slots x 2 halves per warp
// ---------------------------------------------------------------------------
__global__ void k_agg2(int n) {
    int gw = (blockIdx.x * blockDim.x + threadIdx.x) >> 5;
    if (gw >= n) return;
    int lane = threadIdx.x & 31;
    int slot = lane >> 1, h = lane & 1;
    int beg = g_off[gw], end = g_off[gw + 1];
    float4 acc = make_float4(0.f, 0.f, 0.f, 0.f);
    for (int idx = beg + slot; idx < end; idx += 16) {
        int s = g_src[idx];
        float w = g_dis[s];
        float4 v = reinterpret_cast<const float4*>(g_h2)[s * 2 + h];
        acc.x = fmaf(v.x, w, acc.x);
        acc.y = fmaf(v.y, w, acc.y);
        acc.z = fmaf(v.z, w, acc.z);
        acc.w = fmaf(v.w, w, acc.w);
    }
#pragma unroll
    for (int off = 2; off <= 16; off <<= 1) {
        acc.x += __shfl_xor_sync(0xFFFFFFFFu, acc.x, off);
        acc.y += __shfl_xor_sync(0xFFFFFFFFu, acc.y, off);
        acc.z += __shfl_xor_sync(0xFFFFFFFFu, acc.z, off);
        acc.w += __shfl_xor_sync(0xFFFFFFFFu, acc.w, off);
    }
    if (slot == 0) {
        float dd = g_dis[gw], s2 = dd * dd;
        float4 v = reinterpret_cast<const float4*>(g_h2)[gw * 2 + h];
        float4 o;
        o.x = acc.x * dd + v.x * s2;
        o.y = acc.y * dd + v.y * s2;
        o.z = acc.z * dd + v.z * s2;
        o.w = acc.w * dd + v.w * s2;
        reinterpret_cast<float4*>(g_agg2)[gw * 2 + h] = o;
    }
}

// ---------------------------------------------------------------------------
// Output: log_softmax(agg2 + b2)
// ---------------------------------------------------------------------------
__global__ void k_out(const float* __restrict__ b2, float* __restrict__ out, int n) {
    __shared__ float sb2[7];
    if (threadIdx.x < 7) sb2[threadIdx.x] = b2[threadIdx.x];
    __syncthreads();
    int i = blockIdx.x * blockDim.x + threadIdx.x;
    if (i >= n) return;
    float v[7];
    float4 a0 = reinterpret_cast<const float4*>(g_agg2)[i * 2 + 0];
    float4 a1 = reinterpret_cast<const float4*>(g_agg2)[i * 2 + 1];
    v[0] = a0.x + sb2[0]; v[1] = a0.y + sb2[1]; v[2] = a0.z + sb2[2]; v[3] = a0.w + sb2[3];
    v[4] = a1.x + sb2[4]; v[5] = a1.y + sb2[5]; v[6] = a1.z + sb2[6];
    float m = v[0];
#pragma unroll
    for (int c = 1; c < 7; ++c) m = fmaxf(m, v[c]);
    float sum = 0.0f;
#pragma unroll
    for (int c = 0; c < 7; ++c) sum += expf(v[c] - m);
    float lse = logf(sum);
#pragma unroll
    for (int c = 0; c < 7; ++c) out[(size_t)i * 7 + c] = v[c] - m - lse;
}

// ---------------------------------------------------------------------------
extern "C" void kernel_launch(void* const* d_in, const int* in_sizes, int n_in,
                              void* d_out, int out_size) {
    const float* x  = (const float*)d_in[0];
    const int*   ei = (const int*)d_in[1];     // int32 OR int64 (probed on device)
    const float* W1 = (const float*)d_in[2];
    const float* b1 = (const float*)d_in[3];
    const float* W2 = (const float*)d_in[4];
    const float* b2 = (const float*)d_in[5];
    float* out = (float*)d_out;

    const int E = in_sizes[1] / 2;      // 3,200,000 edges
    const int n = in_sizes[0] / F_IN;   // 100,000 nodes
    const int nb = (n + SCAN_BLK - 1) / SCAN_BLK;  // 98

    const int smem = F_IN * SROW * (int)sizeof(float);  // 103,176 B
    cudaFuncSetAttribute(k_gemm1, cudaFuncAttributeMaxDynamicSharedMemorySize, smem);

    const int T = 256;
    k_probe   <<<1, 32>>>(ei, in_sizes[1]);
    k_zero    <<<(n + T - 1) / T, T>>>(n);
    k_count   <<<(E + T - 1) / T, T>>>(ei, E);
    k_blocksum<<<nb, 256>>>(n);
    k_scanbsum<<<1, 128>>>(nb, n);
    k_offsets <<<nb, 256>>>(n);
    k_fill    <<<(E + T - 1) / T, T>>>(ei, E);
    k_dis     <<<(n + T - 1) / T, T>>>(n);
    k_gemm1   <<<(n + 63) / 64, 512, smem>>>(x, W1, n);
    k_agg1    <<<(n + 7) / 8, 256>>>(n);
    k_layer2  <<<(n + T - 1) / T, T>>>(b1, W2, n);
    k_agg2    <<<(n + 7) / 8, 256>>>(n);
    k_out     <<<(n + T - 1) / T, T>>>(b2, out, n);
}